// round 4
// baseline (speedup 1.0000x reference)
#include <cuda_runtime.h>
#include <cuda_bf16.h>
#include <cstdint>

#define BDIM   64
#define IOD    8192
#define OTILE  128
#define KSPLIT 4
#define KQ     (IOD / KSPLIT)      // 2048
#define KC     64
#define NITER  (KQ / KC)           // 32
#define W_BYTES  (OTILE * 128)     // 16384 (128 rows x 64 bf16)
#define X_BYTES  (BDIM * 128)      // 8192 per hi/lo
#define STAGE_BYTES (W_BYTES + 2 * X_BYTES)   // 32768
#define SMEM_TOTAL  (2 * STAGE_BYTES)         // 65536

// scratch (no cudaMalloc allowed)
__device__ __nv_bfloat16 g_xhi[BDIM * IOD];
__device__ __nv_bfloat16 g_xlo[BDIM * IOD];
__device__ float g_part[KSPLIT][BDIM * IOD];   // split-K partials (alpha applied, no bias)

__global__ void prep_x(const float* __restrict__ x) {
    int i = blockIdx.x * blockDim.x + threadIdx.x;   // float4 index
    if (i < (BDIM * IOD) / 4) {
        float4 v = reinterpret_cast<const float4*>(x)[i];
        __nv_bfloat16 h0 = __float2bfloat16(v.x);
        __nv_bfloat16 h1 = __float2bfloat16(v.y);
        __nv_bfloat16 h2 = __float2bfloat16(v.z);
        __nv_bfloat16 h3 = __float2bfloat16(v.w);
        __nv_bfloat162 hi01, hi23, lo01, lo23;
        hi01.x = h0; hi01.y = h1; hi23.x = h2; hi23.y = h3;
        lo01.x = __float2bfloat16(v.x - __bfloat162float(h0));
        lo01.y = __float2bfloat16(v.y - __bfloat162float(h1));
        lo23.x = __float2bfloat16(v.z - __bfloat162float(h2));
        lo23.y = __float2bfloat16(v.w - __bfloat162float(h3));
        reinterpret_cast<__nv_bfloat162*>(g_xhi)[i * 2]     = hi01;
        reinterpret_cast<__nv_bfloat162*>(g_xhi)[i * 2 + 1] = hi23;
        reinterpret_cast<__nv_bfloat162*>(g_xlo)[i * 2]     = lo01;
        reinterpret_cast<__nv_bfloat162*>(g_xlo)[i * 2 + 1] = lo23;
    }
}

// 128B-row XOR swizzle (Swizzle<3,4,3>) — conflict-free STS/cp.async + ldmatrix
__device__ __forceinline__ uint32_t swz(uint32_t off) {
    return off ^ ((off >> 3) & 0x70);
}

__device__ __forceinline__ void ldm_x4(uint32_t& r0, uint32_t& r1,
                                       uint32_t& r2, uint32_t& r3, uint32_t addr) {
    asm volatile("ldmatrix.sync.aligned.m8n8.x4.shared.b16 {%0,%1,%2,%3}, [%4];"
                 : "=r"(r0), "=r"(r1), "=r"(r2), "=r"(r3) : "r"(addr));
}

__device__ __forceinline__ void mma_bf16(float* c,
                                         uint32_t a0, uint32_t a1, uint32_t a2, uint32_t a3,
                                         uint32_t b0, uint32_t b1) {
    asm volatile("mma.sync.aligned.m16n8k16.row.col.f32.bf16.bf16.f32 "
                 "{%0,%1,%2,%3}, {%4,%5,%6,%7}, {%8,%9}, {%0,%1,%2,%3};"
                 : "+f"(c[0]), "+f"(c[1]), "+f"(c[2]), "+f"(c[3])
                 : "r"(a0), "r"(a1), "r"(a2), "r"(a3), "r"(b0), "r"(b1));
}

__device__ __forceinline__ void cp_async16(uint32_t dst, const void* src) {
    asm volatile("cp.async.cg.shared.global [%0], [%1], 16;" :: "r"(dst), "l"(src));
}
#define CP_COMMIT() asm volatile("cp.async.commit_group;" ::: "memory")
#define CP_WAIT0()  asm volatile("cp.async.wait_group 0;"  ::: "memory")

// ternary quantize one fp32 -> bf16 {-1, 0, +1} bit pattern (alpha applied in epilogue)
__device__ __forceinline__ uint32_t quant1(float f, float thr) {
    uint32_t u = __float_as_uint(f);
    return (fabsf(f) > thr) ? (0x3F80u | ((u >> 16) & 0x8000u)) : 0u;
}

// issue cp.async for one X stage (hi+lo)
__device__ __forceinline__ void x_cpasync(uint32_t stage_base, int xm, int xc, int kglob) {
    const __nv_bfloat16* sh = g_xhi + (size_t)xm * IOD + kglob + xc * 16;
    const __nv_bfloat16* sl = g_xlo + (size_t)xm * IOD + kglob + xc * 16;
#pragma unroll
    for (int h = 0; h < 2; ++h) {
        uint32_t off = swz((uint32_t)(xm * 128 + xc * 32 + h * 16));
        cp_async16(stage_base + W_BYTES + off,            sh + h * 8);
        cp_async16(stage_base + W_BYTES + X_BYTES + off,  sl + h * 8);
    }
}

__device__ __forceinline__ void w_load(const float* __restrict__ wp, uint4 wreg[8]) {
#pragma unroll
    for (int p = 0; p < 8; ++p)
        wreg[p] = *reinterpret_cast<const uint4*>(wp + p * 4);
}

__device__ __forceinline__ void w_store(uint32_t stage_base, int wr, int wc,
                                        float thr, const uint4 wreg[8]) {
#pragma unroll
    for (int j = 0; j < 4; ++j) {
        const uint4& u0 = wreg[2 * j];
        const uint4& u1 = wreg[2 * j + 1];
        uint32_t q0 = quant1(__uint_as_float(u0.x), thr);
        uint32_t q1 = quant1(__uint_as_float(u0.y), thr);
        uint32_t q2 = quant1(__uint_as_float(u0.z), thr);
        uint32_t q3 = quant1(__uint_as_float(u0.w), thr);
        uint32_t q4 = quant1(__uint_as_float(u1.x), thr);
        uint32_t q5 = quant1(__uint_as_float(u1.y), thr);
        uint32_t q6 = quant1(__uint_as_float(u1.z), thr);
        uint32_t q7 = quant1(__uint_as_float(u1.w), thr);
        uint4 v;
        v.x = q0 | (q1 << 16);
        v.y = q2 | (q3 << 16);
        v.z = q4 | (q5 << 16);
        v.w = q6 | (q7 << 16);
        uint32_t addr = stage_base + swz((uint32_t)(wr * 128 + wc * 64 + j * 16));
        asm volatile("st.shared.v4.b32 [%0], {%1,%2,%3,%4};"
                     :: "r"(addr), "r"(v.x), "r"(v.y), "r"(v.z), "r"(v.w));
    }
}

__device__ __forceinline__ void mma_stage(uint32_t stage_base,
                                          int m_base, int n_base, int lrow, int lk16,
                                          float acc[2][4][4]) {
#pragma unroll
    for (int ks = 0; ks < 4; ++ks) {
        int kb = ks * 32 + lk16;
        uint32_t b[2][4];
#pragma unroll
        for (int nt2 = 0; nt2 < 2; ++nt2)
            ldm_x4(b[nt2][0], b[nt2][1], b[nt2][2], b[nt2][3],
                   stage_base + swz((uint32_t)((n_base + nt2 * 16 + lrow) * 128 + kb)));
        uint32_t ah[2][4], al[2][4];
#pragma unroll
        for (int mt = 0; mt < 2; ++mt) {
            uint32_t roff = swz((uint32_t)((m_base + mt * 16 + lrow) * 128 + kb));
            ldm_x4(ah[mt][0], ah[mt][1], ah[mt][2], ah[mt][3],
                   stage_base + W_BYTES + roff);
            ldm_x4(al[mt][0], al[mt][1], al[mt][2], al[mt][3],
                   stage_base + W_BYTES + X_BYTES + roff);
        }
#pragma unroll
        for (int mt = 0; mt < 2; ++mt) {
#pragma unroll
            for (int nt2 = 0; nt2 < 2; ++nt2) {
                mma_bf16(acc[mt][nt2 * 2 + 0], ah[mt][0], ah[mt][1], ah[mt][2], ah[mt][3],
                         b[nt2][0], b[nt2][2]);
                mma_bf16(acc[mt][nt2 * 2 + 1], ah[mt][0], ah[mt][1], ah[mt][2], ah[mt][3],
                         b[nt2][1], b[nt2][3]);
                mma_bf16(acc[mt][nt2 * 2 + 0], al[mt][0], al[mt][1], al[mt][2], al[mt][3],
                         b[nt2][0], b[nt2][2]);
                mma_bf16(acc[mt][nt2 * 2 + 1], al[mt][0], al[mt][1], al[mt][2], al[mt][3],
                         b[nt2][1], b[nt2][3]);
            }
        }
    }
}

__global__ __launch_bounds__(256, 2) void qlin(
    const float* __restrict__ wgt,
    const float* __restrict__ alpha)
{
    extern __shared__ __align__(1024) unsigned char smem[];

    const int otile = blockIdx.x & 63;
    const int kq    = blockIdx.x >> 6;
    const int n0    = otile * OTILE;
    const int k0    = kq * KQ;

    const int tid  = threadIdx.x;
    const int lane = tid & 31;
    const int warp = tid >> 5;
    const int m_base = (warp >> 2) * 32;   // 2 warp rows (M=64)
    const int n_base = (warp & 3) * 32;    // 4 warp cols (N=128)

    const uint32_t smem_base = (uint32_t)__cvta_generic_to_shared(smem);

    // W loader: 2 threads per O-row (128 rows), 32 k-cols each
    const int wr = tid >> 1;
    const int wc = tid & 1;
    const float thr = 0.5f * (alpha[n0 + wr] + 1e-8f);
    const float* wp0 = wgt + (size_t)(n0 + wr) * IOD + k0 + wc * 32;

    // X loader: 4 threads per batch row
    const int xm = tid >> 2;
    const int xc = tid & 3;

    const int lrow = lane & 15;
    const int lk16 = (lane >> 4) * 16;

    float acc[2][4][4];
#pragma unroll
    for (int i = 0; i < 2; ++i)
#pragma unroll
        for (int j = 0; j < 4; ++j)
#pragma unroll
            for (int k = 0; k < 4; ++k) acc[i][j][k] = 0.0f;

    uint4 wreg[8];

    // prologue: fill stage 0
    x_cpasync(smem_base, xm, xc, k0);
    CP_COMMIT();
    w_load(wp0, wreg);
    w_store(smem_base, wr, wc, thr, wreg);
    CP_WAIT0();
    __syncthreads();

    for (int it = 0; it < NITER; ++it) {
        const uint32_t cur_base = smem_base + (it & 1) * STAGE_BYTES;
        const uint32_t nxt_base = smem_base + ((it & 1) ^ 1) * STAGE_BYTES;

        if (it + 1 < NITER) {
            x_cpasync(nxt_base, xm, xc, k0 + (it + 1) * KC);
            CP_COMMIT();
            w_load(wp0 + (it + 1) * KC, wreg);
        }

        mma_stage(cur_base, m_base, n_base, lrow, lk16, acc);

        if (it + 1 < NITER) {
            w_store(nxt_base, wr, wc, thr, wreg);
            CP_WAIT0();
        }
        __syncthreads();
    }

    // epilogue: partial[b,o] = alpha[o] * acc   (bias added in reduce)
    float* part = g_part[kq];
#pragma unroll
    for (int mt = 0; mt < 2; ++mt) {
#pragma unroll
        for (int nt = 0; nt < 4; ++nt) {
            int brow = m_base + mt * 16 + (lane >> 2);
            int o0   = n0 + n_base + nt * 8 + (lane & 3) * 2;
            float2 a2 = *reinterpret_cast<const float2*>(alpha + o0);
            float2 v0, v1;
            v0.x = acc[mt][nt][0] * a2.x;
            v0.y = acc[mt][nt][1] * a2.y;
            v1.x = acc[mt][nt][2] * a2.x;
            v1.y = acc[mt][nt][3] * a2.y;
            *reinterpret_cast<float2*>(part + (size_t)brow * IOD + o0)       = v0;
            *reinterpret_cast<float2*>(part + (size_t)(brow + 8) * IOD + o0) = v1;
        }
    }
}

__global__ void reduce_k(const float* __restrict__ bias, float* __restrict__ out) {
    int i = blockIdx.x * blockDim.x + threadIdx.x;     // float4 index
    if (i < (BDIM * IOD) / 4) {
        float4 p0 = reinterpret_cast<const float4*>(g_part[0])[i];
        float4 p1 = reinterpret_cast<const float4*>(g_part[1])[i];
        float4 p2 = reinterpret_cast<const float4*>(g_part[2])[i];
        float4 p3 = reinterpret_cast<const float4*>(g_part[3])[i];
        int o = (i * 4) & (IOD - 1);
        float4 b = *reinterpret_cast<const float4*>(bias + o);
        float4 r;
        r.x = (p0.x + p1.x) + (p2.x + p3.x) + b.x;
        r.y = (p0.y + p1.y) + (p2.y + p3.y) + b.y;
        r.z = (p0.z + p1.z) + (p2.z + p3.z) + b.z;
        r.w = (p0.w + p1.w) + (p2.w + p3.w) + b.w;
        reinterpret_cast<float4*>(out)[i] = r;
    }
}

extern "C" void kernel_launch(void* const* d_in, const int* in_sizes, int n_in,
                              void* d_out, int out_size) {
    const float* x     = (const float*)d_in[0];
    const float* wgt   = (const float*)d_in[1];
    const float* alpha = (const float*)d_in[2];
    const float* bias  = (const float*)d_in[3];
    float* out = (float*)d_out;

    static bool attr_set = false;
    if (!attr_set) {
        cudaFuncSetAttribute(qlin, cudaFuncAttributeMaxDynamicSharedMemorySize, SMEM_TOTAL);
        attr_set = true;
    }

    prep_x<<<((BDIM * IOD / 4) + 255) / 256, 256>>>(x);
    qlin<<<64 * KSPLIT, 256, SMEM_TOTAL>>>(wgt, alpha);
    reduce_k<<<((BDIM * IOD / 4) + 255) / 256, 256>>>(bias, out);
}